// round 1
// baseline (speedup 1.0000x reference)
#include <cuda_runtime.h>
#include <math.h>

#define B_   4
#define S_   512
#define E_   768
#define H_   12
#define D_   64
#define FF_  3072
#define L_   12
#define NTOK (B_*S_)     // 2048
#define BH   (B_*H_)     // 48

#define E3_  (3*E_)      // 2304

// 1/sqrt(768) applied AFTER softmax (faithful to reference)
#define SCALE_INV 0.03608439182435161f

// ---------------- scratch (static __device__, no allocation) ----------------
__device__ float g_h[NTOK*E_];        // ln1 out, later merged-heads buffer
__device__ float g_qkv[NTOK*E3_];
__device__ float g_q[BH*S_*D_];
__device__ float g_k[BH*S_*D_];
__device__ float g_v[BH*S_*D_];
__device__ float g_att[(size_t)BH*S_*S_];
__device__ float g_o[BH*S_*D_];
__device__ float g_oproj[NTOK*E_];
__device__ float g_r1[NTOK*E_];
__device__ float g_f[NTOK*E_];
__device__ float g_ff[NTOK*FF_];
__device__ float g_f2[NTOK*E_];
__device__ float g_x[NTOK*E_];

// ---------------- reductions ----------------
__device__ __forceinline__ float block_reduce(float v, int op /*0 sum, 1 max*/) {
    __shared__ float sh[8];
    int lane = threadIdx.x & 31, wid = threadIdx.x >> 5;
    #pragma unroll
    for (int o = 16; o; o >>= 1) {
        float t = __shfl_xor_sync(0xffffffffu, v, o);
        v = op ? fmaxf(v, t) : (v + t);
    }
    if (lane == 0) sh[wid] = v;
    __syncthreads();
    if (wid == 0) {
        v = (lane < 8) ? sh[lane] : (op ? -INFINITY : 0.0f);
        #pragma unroll
        for (int o = 4; o; o >>= 1) {
            float t = __shfl_xor_sync(0xffffffffu, v, o);
            v = op ? fmaxf(v, t) : (v + t);
        }
        if (lane == 0) sh[0] = v;
    }
    __syncthreads();
    float r = sh[0];
    __syncthreads();   // protect shared reuse across successive calls
    return r;
}

// ---------------- LayerNorm (+ up to two residual adds) ----------------
// out = LN(in)*g + b [+ res1] [+ res2]
__global__ __launch_bounds__(256) void ln_kernel(
    const float* __restrict__ in, const float* __restrict__ g,
    const float* __restrict__ bb, const float* __restrict__ res1,
    const float* __restrict__ res2, float* __restrict__ out)
{
    long long base = (long long)blockIdx.x * E_;
    int t = threadIdx.x;
    float v[3];
    #pragma unroll
    for (int i = 0; i < 3; i++) v[i] = in[base + t + i*256];
    float s  = v[0] + v[1] + v[2];
    float sq = v[0]*v[0] + v[1]*v[1] + v[2]*v[2];
    s  = block_reduce(s, 0);
    sq = block_reduce(sq, 0);
    float mean = s * (1.0f/E_);
    float var  = sq * (1.0f/E_) - mean*mean;
    float rstd = rsqrtf(var + 1e-5f);
    #pragma unroll
    for (int i = 0; i < 3; i++) {
        int c = t + i*256;
        float o = (v[i] - mean) * rstd * g[c] + bb[c];
        if (res1) o += res1[base + c];
        if (res2) o += res2[base + c];
        out[base + c] = o;
    }
}

// ---------------- GEMM: C = A @ B (+bias) (+gelu), batched strides ----------------
// A [M,K] row-major, B [K,N] row-major (NN) or [N,K] row-major (NT).
// All of M%64==0, N%64==0, K%16==0 hold for every call site.
#define BM 64
#define BN 64
#define BK 16

__device__ __forceinline__ float gelu_exact(float x) {
    return 0.5f * x * (1.0f + erff(x * 0.7071067811865476f));
}

template<bool NT>
__global__ __launch_bounds__(256) void gemm_kernel(
    const float* __restrict__ A, const float* __restrict__ Bm,
    const float* __restrict__ bias, float* __restrict__ C,
    int M, int N, int K,
    long long sA, long long sB, long long sC, int act)
{
    A  += (long long)blockIdx.z * sA;
    Bm += (long long)blockIdx.z * sB;
    C  += (long long)blockIdx.z * sC;

    __shared__ float As[BK][BM+4];
    __shared__ float Bs[BK][BN+4];

    int tid = threadIdx.x;
    int bm = blockIdx.y * BM, bn = blockIdx.x * BN;
    int ty = tid >> 4, tx = tid & 15;

    int arow = tid >> 2;            // 0..63
    int acol = (tid & 3) * 4;       // 0..12
    int brow = tid >> 4;            // 0..15  (NN)
    int bcol = (tid & 15) * 4;      // 0..60  (NN)

    float acc[4][4] = {};

    for (int k0 = 0; k0 < K; k0 += BK) {
        float4 a = *(const float4*)&A[(long long)(bm + arow) * K + k0 + acol];
        As[acol+0][arow] = a.x; As[acol+1][arow] = a.y;
        As[acol+2][arow] = a.z; As[acol+3][arow] = a.w;
        if (NT) {
            // B is [N,K]: load contiguous along K, scatter into Bs[k][n]
            float4 b = *(const float4*)&Bm[(long long)(bn + arow) * K + k0 + acol];
            Bs[acol+0][arow] = b.x; Bs[acol+1][arow] = b.y;
            Bs[acol+2][arow] = b.z; Bs[acol+3][arow] = b.w;
        } else {
            float4 b = *(const float4*)&Bm[(long long)(k0 + brow) * N + bn + bcol];
            *(float4*)&Bs[brow][bcol] = b;
        }
        __syncthreads();
        #pragma unroll
        for (int k = 0; k < BK; ++k) {
            float4 ra = *(const float4*)&As[k][ty*4];
            float4 rb = *(const float4*)&Bs[k][tx*4];
            float va[4] = {ra.x, ra.y, ra.z, ra.w};
            float vb[4] = {rb.x, rb.y, rb.z, rb.w};
            #pragma unroll
            for (int i = 0; i < 4; i++)
                #pragma unroll
                for (int j = 0; j < 4; j++)
                    acc[i][j] = fmaf(va[i], vb[j], acc[i][j]);
        }
        __syncthreads();
    }

    float4 bv = make_float4(0.f, 0.f, 0.f, 0.f);
    if (bias) bv = *(const float4*)&bias[bn + tx*4];
    #pragma unroll
    for (int i = 0; i < 4; i++) {
        int row = bm + ty*4 + i;
        float o0 = acc[i][0] + bv.x;
        float o1 = acc[i][1] + bv.y;
        float o2 = acc[i][2] + bv.z;
        float o3 = acc[i][3] + bv.w;
        if (act == 1) {
            o0 = gelu_exact(o0); o1 = gelu_exact(o1);
            o2 = gelu_exact(o2); o3 = gelu_exact(o3);
        }
        *(float4*)&C[(long long)row * N + bn + tx*4] = make_float4(o0, o1, o2, o3);
    }
}

// ---------------- QKV split / head merge ----------------
// qkv[b,s,(h*D+d)*3 + c]  ->  q/k/v[((b*H+h)*S+s)*D + d]
__global__ __launch_bounds__(256) void qkv_split(
    const float* __restrict__ qkv, float* __restrict__ q,
    float* __restrict__ k, float* __restrict__ v)
{
    int i = blockIdx.x * 256 + threadIdx.x;     // over BH*S*D
    int d = i & (D_-1);
    int s = (i >> 6) & (S_-1);
    int h = (i >> 15) % H_;
    int b = i / (D_ * S_ * H_);
    long long src = (long long)(b * S_ + s) * E3_ + (h * D_ + d) * 3;
    q[i] = qkv[src + 0];
    k[i] = qkv[src + 1];
    v[i] = qkv[src + 2];
}

__global__ __launch_bounds__(256) void merge_heads(
    const float* __restrict__ o, float* __restrict__ out)
{
    int i = blockIdx.x * 256 + threadIdx.x;     // over BH*S*D (q-layout)
    int d = i & (D_-1);
    int s = (i >> 6) & (S_-1);
    int h = (i >> 15) % H_;
    int b = i / (D_ * S_ * H_);
    out[(long long)(b * S_ + s) * E_ + h * D_ + d] = o[i];
}

// ---------------- softmax over rows of 512, then * 1/sqrt(768) ----------------
__global__ __launch_bounds__(256) void softmax_div(float* __restrict__ att)
{
    float* p = att + (long long)blockIdx.x * S_;
    int t = threadIdx.x;
    float v0 = p[t], v1 = p[t + 256];
    float m = block_reduce(fmaxf(v0, v1), 1);
    v0 = expf(v0 - m);
    v1 = expf(v1 - m);
    float s = block_reduce(v0 + v1, 0);
    float inv = SCALE_INV / s;
    p[t]       = v0 * inv;
    p[t + 256] = v1 * inv;
}

// ---------------- host orchestration ----------------
extern "C" void kernel_launch(void* const* d_in, const int* in_sizes, int n_in,
                              void* d_out, int out_size)
{
    (void)in_sizes; (void)n_in; (void)out_size;

    const float* x_in  = (const float*)d_in[0];
    const float* Wqkv  = (const float*)d_in[1];
    const float* bqkv  = (const float*)d_in[2];
    const float* Wp    = (const float*)d_in[3];
    const float* bp    = (const float*)d_in[4];
    const float* W1    = (const float*)d_in[5];
    const float* b1    = (const float*)d_in[6];
    const float* W2    = (const float*)d_in[7];
    const float* b2    = (const float*)d_in[8];
    const float* g1    = (const float*)d_in[9];
    const float* be1   = (const float*)d_in[10];
    const float* g2    = (const float*)d_in[11];
    const float* be2   = (const float*)d_in[12];
    const float* g3    = (const float*)d_in[13];
    const float* be3   = (const float*)d_in[14];
    const float* g4    = (const float*)d_in[15];
    const float* be4   = (const float*)d_in[16];

    float *p_h, *p_qkv, *p_q, *p_k, *p_v, *p_att, *p_o, *p_oproj,
          *p_r1, *p_f, *p_ff, *p_f2, *p_x;
    cudaGetSymbolAddress((void**)&p_h, g_h);
    cudaGetSymbolAddress((void**)&p_qkv, g_qkv);
    cudaGetSymbolAddress((void**)&p_q, g_q);
    cudaGetSymbolAddress((void**)&p_k, g_k);
    cudaGetSymbolAddress((void**)&p_v, g_v);
    cudaGetSymbolAddress((void**)&p_att, g_att);
    cudaGetSymbolAddress((void**)&p_o, g_o);
    cudaGetSymbolAddress((void**)&p_oproj, g_oproj);
    cudaGetSymbolAddress((void**)&p_r1, g_r1);
    cudaGetSymbolAddress((void**)&p_f, g_f);
    cudaGetSymbolAddress((void**)&p_ff, g_ff);
    cudaGetSymbolAddress((void**)&p_f2, g_f2);
    cudaGetSymbolAddress((void**)&p_x, g_x);

    cudaMemcpyAsync(p_x, x_in, (size_t)NTOK * E_ * sizeof(float),
                    cudaMemcpyDeviceToDevice, 0);

    const int nqd = BH * S_ * D_;           // 1,572,864

    for (int l = 0; l < L_; ++l) {
        const float* Wqkv_l = Wqkv + (long long)l * E_ * E3_;
        const float* bqkv_l = bqkv + (long long)l * E3_;
        const float* Wp_l   = Wp   + (long long)l * E_ * E_;
        const float* bp_l   = bp   + (long long)l * E_;
        const float* W1_l   = W1   + (long long)l * E_ * FF_;
        const float* b1_l   = b1   + (long long)l * FF_;
        const float* W2_l   = W2   + (long long)l * FF_ * E_;
        const float* b2_l   = b2   + (long long)l * E_;
        const float* g1_l = g1 + (long long)l * E_, *be1_l = be1 + (long long)l * E_;
        const float* g2_l = g2 + (long long)l * E_, *be2_l = be2 + (long long)l * E_;
        const float* g3_l = g3 + (long long)l * E_, *be3_l = be3 + (long long)l * E_;
        const float* g4_l = g4 + (long long)l * E_, *be4_l = be4 + (long long)l * E_;

        // h = LN1(x)
        ln_kernel<<<NTOK, 256>>>(p_x, g1_l, be1_l, nullptr, nullptr, p_h);
        // qkv = h @ Wqkv + bqkv
        gemm_kernel<false><<<dim3(E3_/BN, NTOK/BM, 1), 256>>>(
            p_h, Wqkv_l, bqkv_l, p_qkv, NTOK, E3_, E_, 0, 0, 0, 0);
        // split into Q,K,V [B,H,S,D]
        qkv_split<<<nqd/256, 256>>>(p_qkv, p_q, p_k, p_v);
        // energy = Q @ K^T   (batched NT)
        gemm_kernel<true><<<dim3(S_/BN, S_/BM, BH), 256>>>(
            p_q, p_k, nullptr, p_att, S_, S_, D_,
            (long long)S_*D_, (long long)S_*D_, (long long)S_*S_, 0);
        // att = softmax(energy) / sqrt(E)
        softmax_div<<<BH * S_, 256>>>(p_att);
        // O = att @ V        (batched NN)
        gemm_kernel<false><<<dim3(D_/BN, S_/BM, BH), 256>>>(
            p_att, p_v, nullptr, p_o, S_, D_, S_,
            (long long)S_*S_, (long long)S_*D_, (long long)S_*D_, 0);
        // merge heads -> g_h (reused)
        merge_heads<<<nqd/256, 256>>>(p_o, p_h);
        // oproj = merged @ Wp + bp
        gemm_kernel<false><<<dim3(E_/BN, NTOK/BM, 1), 256>>>(
            p_h, Wp_l, bp_l, p_oproj, NTOK, E_, E_, 0, 0, 0, 0);
        // r1 = LN2(oproj) + x
        ln_kernel<<<NTOK, 256>>>(p_oproj, g2_l, be2_l, p_x, nullptr, p_r1);
        // f = LN3(r1)
        ln_kernel<<<NTOK, 256>>>(p_r1, g3_l, be3_l, nullptr, nullptr, p_f);
        // ff = gelu(f @ W1 + b1)
        gemm_kernel<false><<<dim3(FF_/BN, NTOK/BM, 1), 256>>>(
            p_f, W1_l, b1_l, p_ff, NTOK, FF_, E_, 0, 0, 0, 1);
        // f2 = ff @ W2 + b2
        gemm_kernel<false><<<dim3(E_/BN, NTOK/BM, 1), 256>>>(
            p_ff, W2_l, b2_l, p_f2, NTOK, E_, FF_, 0, 0, 0, 0);
        // x = LN4(f2) + r1 + x   (in-place safe: elementwise read/write same idx)
        ln_kernel<<<NTOK, 256>>>(p_f2, g4_l, be4_l, p_r1, p_x, p_x);
    }

    cudaMemcpyAsync(d_out, p_x, (size_t)NTOK * E_ * sizeof(float),
                    cudaMemcpyDeviceToDevice, 0);
}

// round 2
// speedup vs baseline: 2.4961x; 2.4961x over previous
#include <cuda_runtime.h>
#include <math.h>
#include <stdint.h>

#define B_   4
#define S_   512
#define E_   768
#define H_   12
#define D_   64
#define FF_  3072
#define L_   12
#define NTOK (B_*S_)     // 2048
#define BH   (B_*H_)     // 48
#define E3_  (3*E_)      // 2304

// 1/sqrt(768) applied AFTER softmax (faithful to reference)
#define SCALE_INV 0.03608439182435161f

// ---------------- scratch (static __device__, no allocation) ----------------
__device__ float g_h[NTOK*E_];
__device__ float g_qkv[NTOK*E3_];
__device__ float g_q[BH*S_*D_];
__device__ float g_k[BH*S_*D_];
__device__ float g_v[BH*S_*D_];
__device__ float g_att[(size_t)BH*S_*S_];
__device__ float g_o[BH*S_*D_];
__device__ float g_oproj[NTOK*E_];
__device__ float g_r1[NTOK*E_];
__device__ float g_f[NTOK*E_];
__device__ float g_ff[NTOK*FF_];
__device__ float g_f2[NTOK*E_];
__device__ float g_x[NTOK*E_];

// ---------------- helpers ----------------
__device__ __forceinline__ uint32_t f2tf32(float f) {
    uint32_t u;
    asm("cvt.rna.tf32.f32 %0, %1;" : "=r"(u) : "f"(f));
    return u;
}

__device__ __forceinline__ void mma_tf32(float* c, const uint32_t* a, const uint32_t* b) {
    asm volatile(
        "mma.sync.aligned.m16n8k8.row.col.f32.tf32.tf32.f32 "
        "{%0,%1,%2,%3}, {%4,%5,%6,%7}, {%8,%9}, {%0,%1,%2,%3};"
        : "+f"(c[0]), "+f"(c[1]), "+f"(c[2]), "+f"(c[3])
        : "r"(a[0]), "r"(a[1]), "r"(a[2]), "r"(a[3]), "r"(b[0]), "r"(b[1]));
}

__device__ __forceinline__ float gelu_exact(float x) {
    return 0.5f * x * (1.0f + erff(x * 0.7071067811865476f));
}

// ---------------- tensor-core tf32 GEMM ----------------
// C[M,N] = A[M,K] @ B  (+bias) (+gelu). A row-major.
// NTB=false: B is [K,N] row-major. NTB=true: B is [N,K] row-major (i.e. C=A@B^T).
// Batched over blockIdx.z with strides sA,sB,sC.
template<int BM, int BN, bool NTB, int WRM, int WRN>
__global__ void __launch_bounds__(WRM*WRN*32) gemm_tc(
    const float* __restrict__ A, const float* __restrict__ Bm,
    const float* __restrict__ bias, float* __restrict__ C,
    int M, int N, int K,
    long long sA, long long sB, long long sC, int act)
{
    constexpr int BK = 32;
    constexpr int THREADS = WRM * WRN * 32;
    constexpr int WM = BM / WRM;           // 64
    constexpr int WN = BN / WRN;           // 32
    constexpr int MT = WM / 16;            // 4
    constexpr int NTL = WN / 8;            // 4
    constexpr int ASTR = BK + 4;           // 36
    constexpr int BSTR = NTB ? (BK + 4) : (BN + 8);
    constexpr int BROWS = NTB ? BN : BK;
    constexpr int ASZ = BM * ASTR;
    constexpr int BSZ = BROWS * BSTR;
    constexpr int AF4 = BM * BK / 4 / THREADS;
    constexpr int BF4 = BM > 0 ? (BN * BK / 4 / THREADS) : 0;

    extern __shared__ uint32_t sm[];
    uint32_t* As = sm;                 // [2][ASZ]
    uint32_t* Bs = sm + 2 * ASZ;       // [2][BSZ]

    A  += (long long)blockIdx.z * sA;
    Bm += (long long)blockIdx.z * sB;
    C  += (long long)blockIdx.z * sC;

    const int tid  = threadIdx.x;
    const int lane = tid & 31;
    const int warp = tid >> 5;
    const int wm = (warp % WRM) * WM;
    const int wn = (warp / WRM) * WN;
    const int bm = blockIdx.y * BM;
    const int bn = blockIdx.x * BN;

    float stageA[AF4 * 4];
    float stageB[BF4 * 4];
    float acc[MT][NTL][4] = {};

    const int niter = K / BK;

    // ---- LDG of tile `it` into registers ----
    auto ldg_tiles = [&](int k0) {
        #pragma unroll
        for (int r = 0; r < AF4; r++) {
            int f4 = tid + r * THREADS;
            int row = f4 / (BK / 4), c4 = f4 % (BK / 4);
            float4 v = *(const float4*)&A[(long long)(bm + row) * K + k0 + c4 * 4];
            stageA[r*4+0] = v.x; stageA[r*4+1] = v.y;
            stageA[r*4+2] = v.z; stageA[r*4+3] = v.w;
        }
        if (NTB) {
            #pragma unroll
            for (int r = 0; r < BF4; r++) {
                int f4 = tid + r * THREADS;
                int row = f4 / (BK / 4), c4 = f4 % (BK / 4);
                float4 v = *(const float4*)&Bm[(long long)(bn + row) * K + k0 + c4 * 4];
                stageB[r*4+0] = v.x; stageB[r*4+1] = v.y;
                stageB[r*4+2] = v.z; stageB[r*4+3] = v.w;
            }
        } else {
            #pragma unroll
            for (int r = 0; r < BF4; r++) {
                int f4 = tid + r * THREADS;
                int row = f4 / (BN / 4), c4 = f4 % (BN / 4);
                float4 v = *(const float4*)&Bm[(long long)(k0 + row) * N + bn + c4 * 4];
                stageB[r*4+0] = v.x; stageB[r*4+1] = v.y;
                stageB[r*4+2] = v.z; stageB[r*4+3] = v.w;
            }
        }
    };

    // ---- cvt + STS into buffer `buf` ----
    auto sts_tiles = [&](int buf) {
        #pragma unroll
        for (int r = 0; r < AF4; r++) {
            int f4 = tid + r * THREADS;
            int row = f4 / (BK / 4), c4 = f4 % (BK / 4);
            uint32_t* p = &As[buf * ASZ + row * ASTR + c4 * 4];
            p[0] = f2tf32(stageA[r*4+0]); p[1] = f2tf32(stageA[r*4+1]);
            p[2] = f2tf32(stageA[r*4+2]); p[3] = f2tf32(stageA[r*4+3]);
        }
        #pragma unroll
        for (int r = 0; r < BF4; r++) {
            int f4 = tid + r * THREADS;
            int row, c4;
            if (NTB) { row = f4 / (BK / 4); c4 = f4 % (BK / 4); }
            else     { row = f4 / (BN / 4); c4 = f4 % (BN / 4); }
            uint32_t* p = &Bs[buf * BSZ + row * BSTR + c4 * 4];
            p[0] = f2tf32(stageB[r*4+0]); p[1] = f2tf32(stageB[r*4+1]);
            p[2] = f2tf32(stageB[r*4+2]); p[3] = f2tf32(stageB[r*4+3]);
        }
    };

    // ---- compute over buffer `buf` ----
    auto compute = [&](int buf) {
        #pragma unroll
        for (int kk = 0; kk < 4; kk++) {
            uint32_t af[MT][4];
            {
                int r0 = wm + (lane >> 2);
                int c0 = kk * 8 + (lane & 3);
                #pragma unroll
                for (int i = 0; i < MT; i++) {
                    const uint32_t* p = &As[buf * ASZ + (r0 + i * 16) * ASTR + c0];
                    af[i][0] = p[0];
                    af[i][1] = p[8 * ASTR];
                    af[i][2] = p[4];
                    af[i][3] = p[8 * ASTR + 4];
                }
            }
            uint32_t bf[NTL][4];
            #pragma unroll
            for (int j = 0; j < NTL; j++) {
                if (NTB) {
                    const uint32_t* p = &Bs[buf * BSZ + (wn + j * 8 + (lane >> 2)) * BSTR
                                            + kk * 8 + (lane & 3)];
                    bf[j][0] = p[0];
                    bf[j][1] = p[4];
                } else {
                    const uint32_t* p = &Bs[buf * BSZ + (kk * 8 + (lane & 3)) * BSTR
                                            + wn + j * 8 + (lane >> 2)];
                    bf[j][0] = p[0];
                    bf[j][1] = p[4 * BSTR];
                }
            }
            #pragma unroll
            for (int i = 0; i < MT; i++)
                #pragma unroll
                for (int j = 0; j < NTL; j++)
                    mma_tf32(acc[i][j], af[i], bf[j]);
        }
    };

    // ---- pipelined main loop ----
    ldg_tiles(0);
    sts_tiles(0);
    __syncthreads();
    for (int it = 0; it < niter; ++it) {
        if (it + 1 < niter) ldg_tiles((it + 1) * BK);
        compute(it & 1);
        if (it + 1 < niter) {
            sts_tiles((it + 1) & 1);
            __syncthreads();
        }
    }

    // ---- epilogue ----
    #pragma unroll
    for (int i = 0; i < MT; i++) {
        #pragma unroll
        for (int j = 0; j < NTL; j++) {
            int row = bm + wm + i * 16 + (lane >> 2);
            int col = bn + wn + j * 8 + (lane & 3) * 2;
            float2 bv = make_float2(0.f, 0.f);
            if (bias) bv = *(const float2*)&bias[col];
            float o0 = acc[i][j][0] + bv.x;
            float o1 = acc[i][j][1] + bv.y;
            float o2 = acc[i][j][2] + bv.x;
            float o3 = acc[i][j][3] + bv.y;
            if (act == 1) {
                o0 = gelu_exact(o0); o1 = gelu_exact(o1);
                o2 = gelu_exact(o2); o3 = gelu_exact(o3);
            }
            *(float2*)&C[(long long)row * N + col]       = make_float2(o0, o1);
            *(float2*)&C[(long long)(row + 8) * N + col] = make_float2(o2, o3);
        }
    }
}

// ---------------- reductions ----------------
__device__ __forceinline__ float block_reduce(float v, int op /*0 sum, 1 max*/) {
    __shared__ float sh[8];
    int lane = threadIdx.x & 31, wid = threadIdx.x >> 5;
    #pragma unroll
    for (int o = 16; o; o >>= 1) {
        float t = __shfl_xor_sync(0xffffffffu, v, o);
        v = op ? fmaxf(v, t) : (v + t);
    }
    if (lane == 0) sh[wid] = v;
    __syncthreads();
    if (wid == 0) {
        v = (lane < 8) ? sh[lane] : (op ? -INFINITY : 0.0f);
        #pragma unroll
        for (int o = 4; o; o >>= 1) {
            float t = __shfl_xor_sync(0xffffffffu, v, o);
            v = op ? fmaxf(v, t) : (v + t);
        }
        if (lane == 0) sh[0] = v;
    }
    __syncthreads();
    float r = sh[0];
    __syncthreads();
    return r;
}

// ---------------- LayerNorm (+ up to two residual adds) ----------------
__global__ __launch_bounds__(256) void ln_kernel(
    const float* __restrict__ in, const float* __restrict__ g,
    const float* __restrict__ bb, const float* __restrict__ res1,
    const float* __restrict__ res2, float* __restrict__ out)
{
    long long base = (long long)blockIdx.x * E_;
    int t = threadIdx.x;
    float v[3];
    #pragma unroll
    for (int i = 0; i < 3; i++) v[i] = in[base + t + i*256];
    float s  = v[0] + v[1] + v[2];
    float sq = v[0]*v[0] + v[1]*v[1] + v[2]*v[2];
    s  = block_reduce(s, 0);
    sq = block_reduce(sq, 0);
    float mean = s * (1.0f/E_);
    float var  = sq * (1.0f/E_) - mean*mean;
    float rstd = rsqrtf(var + 1e-5f);
    #pragma unroll
    for (int i = 0; i < 3; i++) {
        int c = t + i*256;
        float o = (v[i] - mean) * rstd * g[c] + bb[c];
        if (res1) o += res1[base + c];
        if (res2) o += res2[base + c];
        out[base + c] = o;
    }
}

// ---------------- QKV split / head merge ----------------
__global__ __launch_bounds__(256) void qkv_split(
    const float* __restrict__ qkv, float* __restrict__ q,
    float* __restrict__ k, float* __restrict__ v)
{
    int i = blockIdx.x * 256 + threadIdx.x;     // over BH*S*D
    int d = i & (D_-1);
    int s = (i >> 6) & (S_-1);
    int h = (i >> 15) % H_;
    int b = i / (D_ * S_ * H_);
    long long src = (long long)(b * S_ + s) * E3_ + (h * D_ + d) * 3;
    q[i] = qkv[src + 0];
    k[i] = qkv[src + 1];
    v[i] = qkv[src + 2];
}

__global__ __launch_bounds__(256) void merge_heads(
    const float* __restrict__ o, float* __restrict__ out)
{
    int i = blockIdx.x * 256 + threadIdx.x;
    int d = i & (D_-1);
    int s = (i >> 6) & (S_-1);
    int h = (i >> 15) % H_;
    int b = i / (D_ * S_ * H_);
    out[(long long)(b * S_ + s) * E_ + h * D_ + d] = o[i];
}

// ---------------- softmax rows of 512, then * 1/sqrt(768) ----------------
__global__ __launch_bounds__(256) void softmax_div(float* __restrict__ att)
{
    float* p = att + (long long)blockIdx.x * S_;
    int t = threadIdx.x;
    float v0 = p[t], v1 = p[t + 256];
    float m = block_reduce(fmaxf(v0, v1), 1);
    v0 = expf(v0 - m);
    v1 = expf(v1 - m);
    float s = block_reduce(v0 + v1, 0);
    float inv = SCALE_INV / s;
    p[t]       = v0 * inv;
    p[t + 256] = v1 * inv;
}

// ---------------- host orchestration ----------------
#define SMEM_NN128 ((2*(128*36) + 2*(32*136)) * 4)   // 71680
#define SMEM_NT128 ((2*(128*36) + 2*(128*36)) * 4)   // 73728
#define SMEM_NN64  ((2*(128*36) + 2*(32*72))  * 4)   // 55296

extern "C" void kernel_launch(void* const* d_in, const int* in_sizes, int n_in,
                              void* d_out, int out_size)
{
    (void)in_sizes; (void)n_in; (void)out_size;

    const float* x_in  = (const float*)d_in[0];
    const float* Wqkv  = (const float*)d_in[1];
    const float* bqkv  = (const float*)d_in[2];
    const float* Wp    = (const float*)d_in[3];
    const float* bp    = (const float*)d_in[4];
    const float* W1    = (const float*)d_in[5];
    const float* b1    = (const float*)d_in[6];
    const float* W2    = (const float*)d_in[7];
    const float* b2    = (const float*)d_in[8];
    const float* g1    = (const float*)d_in[9];
    const float* be1   = (const float*)d_in[10];
    const float* g2    = (const float*)d_in[11];
    const float* be2   = (const float*)d_in[12];
    const float* g3    = (const float*)d_in[13];
    const float* be3   = (const float*)d_in[14];
    const float* g4    = (const float*)d_in[15];
    const float* be4   = (const float*)d_in[16];

    static bool attr_done = false;
    if (!attr_done) {
        cudaFuncSetAttribute(gemm_tc<128,128,false,2,4>,
                             cudaFuncAttributeMaxDynamicSharedMemorySize, SMEM_NN128);
        cudaFuncSetAttribute(gemm_tc<128,128,true,2,4>,
                             cudaFuncAttributeMaxDynamicSharedMemorySize, SMEM_NT128);
        cudaFuncSetAttribute(gemm_tc<128,64,false,2,2>,
                             cudaFuncAttributeMaxDynamicSharedMemorySize, SMEM_NN64);
        attr_done = true;
    }

    float *p_h, *p_qkv, *p_q, *p_k, *p_v, *p_att, *p_o, *p_oproj,
          *p_r1, *p_f, *p_ff, *p_f2, *p_x;
    cudaGetSymbolAddress((void**)&p_h, g_h);
    cudaGetSymbolAddress((void**)&p_qkv, g_qkv);
    cudaGetSymbolAddress((void**)&p_q, g_q);
    cudaGetSymbolAddress((void**)&p_k, g_k);
    cudaGetSymbolAddress((void**)&p_v, g_v);
    cudaGetSymbolAddress((void**)&p_att, g_att);
    cudaGetSymbolAddress((void**)&p_o, g_o);
    cudaGetSymbolAddress((void**)&p_oproj, g_oproj);
    cudaGetSymbolAddress((void**)&p_r1, g_r1);
    cudaGetSymbolAddress((void**)&p_f, g_f);
    cudaGetSymbolAddress((void**)&p_ff, g_ff);
    cudaGetSymbolAddress((void**)&p_f2, g_f2);
    cudaGetSymbolAddress((void**)&p_x, g_x);

    cudaMemcpyAsync(p_x, x_in, (size_t)NTOK * E_ * sizeof(float),
                    cudaMemcpyDeviceToDevice, 0);

    const int nqd = BH * S_ * D_;

    for (int l = 0; l < L_; ++l) {
        const float* Wqkv_l = Wqkv + (long long)l * E_ * E3_;
        const float* bqkv_l = bqkv + (long long)l * E3_;
        const float* Wp_l   = Wp   + (long long)l * E_ * E_;
        const float* bp_l   = bp   + (long long)l * E_;
        const float* W1_l   = W1   + (long long)l * E_ * FF_;
        const float* b1_l   = b1   + (long long)l * FF_;
        const float* W2_l   = W2   + (long long)l * FF_ * E_;
        const float* b2_l   = b2   + (long long)l * E_;
        const float* g1_l = g1 + (long long)l * E_, *be1_l = be1 + (long long)l * E_;
        const float* g2_l = g2 + (long long)l * E_, *be2_l = be2 + (long long)l * E_;
        const float* g3_l = g3 + (long long)l * E_, *be3_l = be3 + (long long)l * E_;
        const float* g4_l = g4 + (long long)l * E_, *be4_l = be4 + (long long)l * E_;

        // h = LN1(x)
        ln_kernel<<<NTOK, 256>>>(p_x, g1_l, be1_l, nullptr, nullptr, p_h);
        // qkv = h @ Wqkv + bqkv
        gemm_tc<128,128,false,2,4><<<dim3(E3_/128, NTOK/128, 1), 256, SMEM_NN128>>>(
            p_h, Wqkv_l, bqkv_l, p_qkv, NTOK, E3_, E_, 0, 0, 0, 0);
        // split into Q,K,V [B,H,S,D]
        qkv_split<<<nqd/256, 256>>>(p_qkv, p_q, p_k, p_v);
        // energy = Q @ K^T   (batched, B stored [N,K])
        gemm_tc<128,128,true,2,4><<<dim3(S_/128, S_/128, BH), 256, SMEM_NT128>>>(
            p_q, p_k, nullptr, p_att, S_, S_, D_,
            (long long)S_*D_, (long long)S_*D_, (long long)S_*S_, 0);
        // att = softmax(energy) / sqrt(E)
        softmax_div<<<BH * S_, 256>>>(p_att);
        // O = att @ V        (batched NN, N=64)
        gemm_tc<128,64,false,2,2><<<dim3(1, S_/128, BH), 128, SMEM_NN64>>>(
            p_att, p_v, nullptr, p_o, S_, D_, S_,
            (long long)S_*S_, (long long)S_*D_, (long long)S_*D_, 0);
        // merge heads -> p_h
        merge_heads<<<nqd/256, 256>>>(p_o, p_h);
        // oproj = merged @ Wp + bp
        gemm_tc<128,128,false,2,4><<<dim3(E_/128, NTOK/128, 1), 256, SMEM_NN128>>>(
            p_h, Wp_l, bp_l, p_oproj, NTOK, E_, E_, 0, 0, 0, 0);
        // r1 = LN2(oproj) + x
        ln_kernel<<<NTOK, 256>>>(p_oproj, g2_l, be2_l, p_x, nullptr, p_r1);
        // f = LN3(r1)
        ln_kernel<<<NTOK, 256>>>(p_r1, g3_l, be3_l, nullptr, nullptr, p_f);
        // ff = gelu(f @ W1 + b1)
        gemm_tc<128,128,false,2,4><<<dim3(FF_/128, NTOK/128, 1), 256, SMEM_NN128>>>(
            p_f, W1_l, b1_l, p_ff, NTOK, FF_, E_, 0, 0, 0, 1);
        // f2 = ff @ W2 + b2
        gemm_tc<128,128,false,2,4><<<dim3(E_/128, NTOK/128, 1), 256, SMEM_NN128>>>(
            p_ff, W2_l, b2_l, p_f2, NTOK, E_, FF_, 0, 0, 0, 0);
        // x = LN4(f2) + r1 + x
        ln_kernel<<<NTOK, 256>>>(p_f2, g4_l, be4_l, p_r1, p_x, p_x);
    }

    cudaMemcpyAsync(d_out, p_x, (size_t)NTOK * E_ * sizeof(float),
                    cudaMemcpyDeviceToDevice, 0);
}

// round 3
// speedup vs baseline: 2.7430x; 1.0989x over previous
#include <cuda_runtime.h>
#include <math.h>
#include <stdint.h>

#define B_   4
#define S_   512
#define E_   768
#define H_   12
#define D_   64
#define FF_  3072
#define L_   12
#define NTOK (B_*S_)     // 2048
#define BH   (B_*H_)     // 48
#define E3_  (3*E_)      // 2304

#define SCALE_INV 0.03608439182435161f   // 1/sqrt(768), applied AFTER softmax

// ---------------- scratch (static __device__, no allocation) ----------------
__device__ float g_h[NTOK*E_];
__device__ float g_q[BH*S_*D_];
__device__ float g_k[BH*S_*D_];
__device__ float g_v[BH*S_*D_];
__device__ float g_att[(size_t)BH*S_*S_];
__device__ float g_merged[NTOK*E_];
__device__ float g_oproj[NTOK*E_];
__device__ float g_r1[NTOK*E_];
__device__ float g_f[NTOK*E_];
__device__ float g_ff[NTOK*FF_];
__device__ float g_f2[NTOK*E_];
__device__ float g_x[NTOK*E_];
// tf32-rounded weight copies
__device__ float g_Wqkv_t[(size_t)L_*E_*E3_];
__device__ float g_Wp_t[(size_t)L_*E_*E_];
__device__ float g_W1_t[(size_t)L_*E_*FF_];
__device__ float g_W2_t[(size_t)L_*FF_*E_];

// ---------------- helpers ----------------
__device__ __forceinline__ uint32_t f2tf32(float f) {
    uint32_t u;
    asm("cvt.rna.tf32.f32 %0, %1;" : "=r"(u) : "f"(f));
    return u;
}
__device__ __forceinline__ float f2tf32f(float f) { return __uint_as_float(f2tf32(f)); }

__device__ __forceinline__ void mma_tf32(float* c, const uint32_t* a, const uint32_t* b) {
    asm volatile(
        "mma.sync.aligned.m16n8k8.row.col.f32.tf32.tf32.f32 "
        "{%0,%1,%2,%3}, {%4,%5,%6,%7}, {%8,%9}, {%0,%1,%2,%3};"
        : "+f"(c[0]), "+f"(c[1]), "+f"(c[2]), "+f"(c[3])
        : "r"(a[0]), "r"(a[1]), "r"(a[2]), "r"(a[3]), "r"(b[0]), "r"(b[1]));
}

__device__ __forceinline__ void cp_async16(void* smem, const void* gmem) {
    uint32_t s = (uint32_t)__cvta_generic_to_shared(smem);
    asm volatile("cp.async.cg.shared.global [%0], [%1], 16;\n" :: "r"(s), "l"(gmem));
}
__device__ __forceinline__ void cp_commit() {
    asm volatile("cp.async.commit_group;\n");
}
template<int N> __device__ __forceinline__ void cp_wait() {
    asm volatile("cp.async.wait_group %0;\n" :: "n"(N));
}

__device__ __forceinline__ float gelu_exact(float x) {
    return 0.5f * x * (1.0f + erff(x * 0.7071067811865476f));
}

// ---------------- tensor-core tf32 GEMM, cp.async 3-stage ----------------
// C[M,N] = A[M,K] @ B (+bias). Inputs must already be tf32-rounded fp32.
// NTB=false: B [K,N] row-major; NTB=true: B [N,K] row-major (C = A@B^T).
// act: 0 plain; 1 gelu + tf32-round output; 2 qkv-split scatter; 3 merge-heads.
template<int BM, int BN, bool NTB, int WRM, int WRN>
__global__ void __launch_bounds__(WRM*WRN*32, 2) gemm_cp(
    const float* __restrict__ A, const float* __restrict__ Bm,
    const float* __restrict__ bias, float* __restrict__ C,
    int M, int N, int K,
    long long sA, long long sB, long long sC, int act,
    float* __restrict__ qp, float* __restrict__ kp, float* __restrict__ vp)
{
    constexpr int BK = 32;
    constexpr int STAGES = 3;
    constexpr int THREADS = WRM * WRN * 32;
    constexpr int WM = BM / WRM;
    constexpr int WN = BN / WRN;
    constexpr int MT = WM / 16;
    constexpr int NTL = WN / 8;
    constexpr int ASTR = BK + 4;                     // 36
    constexpr int BSTR = NTB ? (BK + 4) : (BN + 8);
    constexpr int BROWS = NTB ? BN : BK;
    constexpr int ASZ = BM * ASTR;
    constexpr int BSZ = BROWS * BSTR;
    constexpr int AC = BM * BK / 4 / THREADS;        // float4 chunks per thread (A)
    constexpr int BC = BN * BK / 4 / THREADS;        // (B)

    extern __shared__ uint32_t sm[];
    uint32_t* As = sm;                     // [STAGES][ASZ]
    uint32_t* Bs = sm + STAGES * ASZ;      // [STAGES][BSZ]

    A  += (long long)blockIdx.z * sA;
    Bm += (long long)blockIdx.z * sB;
    C  += (long long)blockIdx.z * sC;

    const int tid  = threadIdx.x;
    const int lane = tid & 31;
    const int warp = tid >> 5;
    const int wm = (warp % WRM) * WM;
    const int wn = (warp / WRM) * WN;
    const int bm = blockIdx.y * BM;
    const int bn = blockIdx.x * BN;

    const int niter = K / BK;

    float acc[MT][NTL][4] = {};

    auto issue = [&](int s) {
        int buf = s % STAGES;
        int k0 = s * BK;
        #pragma unroll
        for (int r = 0; r < AC; r++) {
            int f4 = tid + r * THREADS;
            int row = f4 / (BK / 4), c4 = f4 % (BK / 4);
            cp_async16(&As[buf * ASZ + row * ASTR + c4 * 4],
                       &A[(long long)(bm + row) * K + k0 + c4 * 4]);
        }
        #pragma unroll
        for (int r = 0; r < BC; r++) {
            int f4 = tid + r * THREADS;
            if (NTB) {
                int row = f4 / (BK / 4), c4 = f4 % (BK / 4);
                cp_async16(&Bs[buf * BSZ + row * BSTR + c4 * 4],
                           &Bm[(long long)(bn + row) * K + k0 + c4 * 4]);
            } else {
                int row = f4 / (BN / 4), c4 = f4 % (BN / 4);
                cp_async16(&Bs[buf * BSZ + row * BSTR + c4 * 4],
                           &Bm[(long long)(k0 + row) * N + bn + c4 * 4]);
            }
        }
    };

    auto compute = [&](int buf) {
        const uint32_t* Ab = &As[buf * ASZ];
        const uint32_t* Bb = &Bs[buf * BSZ];
        #pragma unroll
        for (int kk = 0; kk < 4; kk++) {
            uint32_t af[MT][4];
            {
                int r0 = wm + (lane >> 2);
                int c0 = kk * 8 + (lane & 3);
                #pragma unroll
                for (int i = 0; i < MT; i++) {
                    const uint32_t* p = &Ab[(r0 + i * 16) * ASTR + c0];
                    af[i][0] = p[0];
                    af[i][1] = p[8 * ASTR];
                    af[i][2] = p[4];
                    af[i][3] = p[8 * ASTR + 4];
                }
            }
            uint32_t bf[NTL][2];
            #pragma unroll
            for (int j = 0; j < NTL; j++) {
                if (NTB) {
                    const uint32_t* p = &Bb[(wn + j * 8 + (lane >> 2)) * BSTR
                                            + kk * 8 + (lane & 3)];
                    bf[j][0] = p[0];
                    bf[j][1] = p[4];
                } else {
                    const uint32_t* p = &Bb[(kk * 8 + (lane & 3)) * BSTR
                                            + wn + j * 8 + (lane >> 2)];
                    bf[j][0] = p[0];
                    bf[j][1] = p[4 * BSTR];
                }
            }
            #pragma unroll
            for (int i = 0; i < MT; i++)
                #pragma unroll
                for (int j = 0; j < NTL; j++)
                    mma_tf32(acc[i][j], af[i], bf[j]);
        }
    };

    // prologue: issue STAGES-1 stages
    #pragma unroll
    for (int s = 0; s < STAGES - 1; s++) {
        if (s < niter) issue(s);
        cp_commit();
    }
    // main loop
    for (int it = 0; it < niter; ++it) {
        cp_wait<STAGES - 2>();
        __syncthreads();
        int nxt = it + STAGES - 1;
        if (nxt < niter) issue(nxt);
        cp_commit();
        compute(it % STAGES);
    }

    // ---- epilogue ----
    const int z = blockIdx.z;
    #pragma unroll
    for (int i = 0; i < MT; i++) {
        #pragma unroll
        for (int j = 0; j < NTL; j++) {
            int row = bm + wm + i * 16 + (lane >> 2);
            int col = bn + wn + j * 8 + (lane & 3) * 2;
            float2 bv = make_float2(0.f, 0.f);
            if (bias) bv = *(const float2*)&bias[col];
            float o[2][2] = {{acc[i][j][0] + bv.x, acc[i][j][1] + bv.y},
                             {acc[i][j][2] + bv.x, acc[i][j][3] + bv.y}};
            if (act == 0) {
                *(float2*)&C[(long long)row * N + col]       = make_float2(o[0][0], o[0][1]);
                *(float2*)&C[(long long)(row + 8) * N + col] = make_float2(o[1][0], o[1][1]);
            } else if (act == 1) {
                // gelu + tf32-round (feeds next GEMM as A)
                *(float2*)&C[(long long)row * N + col] =
                    make_float2(f2tf32f(gelu_exact(o[0][0])), f2tf32f(gelu_exact(o[0][1])));
                *(float2*)&C[(long long)(row + 8) * N + col] =
                    make_float2(f2tf32f(gelu_exact(o[1][0])), f2tf32f(gelu_exact(o[1][1])));
            } else if (act == 2) {
                // qkv split: n -> (c = n%3 selects q/k/v, hd = n/3)
                #pragma unroll
                for (int r = 0; r < 2; r++) {
                    int rr = row + r * 8;
                    int b = rr >> 9, s = rr & 511;
                    #pragma unroll
                    for (int cc = 0; cc < 2; cc++) {
                        int n = col + cc;
                        int c = n % 3, hd = n / 3;
                        int h = hd >> 6, d = hd & 63;
                        long long idx = ((long long)(b * H_ + h) * S_ + s) * D_ + d;
                        float val = f2tf32f(o[r][cc]);
                        if (c == 0) qp[idx] = val;
                        else if (c == 1) kp[idx] = val;
                        else vp[idx] = val;
                    }
                }
            } else {
                // merge heads: z = b*H + h, write [b,s,h*64+d], tf32-rounded
                int b = z / H_, h = z % H_;
                #pragma unroll
                for (int r = 0; r < 2; r++) {
                    int rr = row + r * 8;
                    *(float2*)&C[((long long)(b * S_ + rr)) * E_ + h * D_ + col] =
                        make_float2(f2tf32f(o[r][0]), f2tf32f(o[r][1]));
                }
            }
        }
    }
}

// ---------------- reductions ----------------
__device__ __forceinline__ float block_reduce(float v, int op /*0 sum, 1 max*/) {
    __shared__ float sh[8];
    int lane = threadIdx.x & 31, wid = threadIdx.x >> 5;
    #pragma unroll
    for (int o = 16; o; o >>= 1) {
        float t = __shfl_xor_sync(0xffffffffu, v, o);
        v = op ? fmaxf(v, t) : (v + t);
    }
    if (lane == 0) sh[wid] = v;
    __syncthreads();
    if (wid == 0) {
        v = (lane < 8) ? sh[lane] : (op ? -INFINITY : 0.0f);
        #pragma unroll
        for (int o = 4; o; o >>= 1) {
            float t = __shfl_xor_sync(0xffffffffu, v, o);
            v = op ? fmaxf(v, t) : (v + t);
        }
        if (lane == 0) sh[0] = v;
    }
    __syncthreads();
    float r = sh[0];
    __syncthreads();
    return r;
}

// ---------------- LayerNorm (+ up to two residual adds, optional tf32 out) --
__global__ __launch_bounds__(256) void ln_kernel(
    const float* __restrict__ in, const float* __restrict__ g,
    const float* __restrict__ bb, const float* __restrict__ res1,
    const float* __restrict__ res2, float* __restrict__ out, int docvt)
{
    long long base = (long long)blockIdx.x * E_;
    int t = threadIdx.x;
    float v[3];
    #pragma unroll
    for (int i = 0; i < 3; i++) v[i] = in[base + t + i*256];
    float s  = v[0] + v[1] + v[2];
    float sq = v[0]*v[0] + v[1]*v[1] + v[2]*v[2];
    s  = block_reduce(s, 0);
    sq = block_reduce(sq, 0);
    float mean = s * (1.0f/E_);
    float var  = sq * (1.0f/E_) - mean*mean;
    float rstd = rsqrtf(var + 1e-5f);
    #pragma unroll
    for (int i = 0; i < 3; i++) {
        int c = t + i*256;
        float o = (v[i] - mean) * rstd * g[c] + bb[c];
        if (res1) o += res1[base + c];
        if (res2) o += res2[base + c];
        if (docvt) o = f2tf32f(o);
        out[base + c] = o;
    }
}

// ---------------- softmax rows of 512, * 1/sqrt(768), tf32 out -------------
__global__ __launch_bounds__(256) void softmax_div(float* __restrict__ att)
{
    float* p = att + (long long)blockIdx.x * S_;
    int t = threadIdx.x;
    float v0 = p[t], v1 = p[t + 256];
    float m = block_reduce(fmaxf(v0, v1), 1);
    v0 = expf(v0 - m);
    v1 = expf(v1 - m);
    float s = block_reduce(v0 + v1, 0);
    float inv = SCALE_INV / s;
    p[t]       = f2tf32f(v0 * inv);
    p[t + 256] = f2tf32f(v1 * inv);
}

// ---------------- weight tf32 pre-rounding ----------------
__global__ __launch_bounds__(256) void cvt_tf32_kernel(
    const float* __restrict__ in, float* __restrict__ out, long long n4)
{
    long long i = ((long long)blockIdx.x * 256 + threadIdx.x);
    if (i >= n4) return;
    float4 v = *(const float4*)&in[i * 4];
    v.x = f2tf32f(v.x); v.y = f2tf32f(v.y);
    v.z = f2tf32f(v.z); v.w = f2tf32f(v.w);
    *(float4*)&out[i * 4] = v;
}

// ---------------- host orchestration ----------------
#define SMEM_NN128 ((3*(128*36) + 3*(32*136)) * 4)   // 107520
#define SMEM_NT128 ((3*(128*36) + 3*(128*36)) * 4)   // 110592
#define SMEM_NN64  ((3*(128*36) + 3*(32*72))  * 4)   // 82944

extern "C" void kernel_launch(void* const* d_in, const int* in_sizes, int n_in,
                              void* d_out, int out_size)
{
    (void)in_sizes; (void)n_in; (void)out_size;

    const float* x_in  = (const float*)d_in[0];
    const float* Wqkv  = (const float*)d_in[1];
    const float* bqkv  = (const float*)d_in[2];
    const float* Wp    = (const float*)d_in[3];
    const float* bp    = (const float*)d_in[4];
    const float* W1    = (const float*)d_in[5];
    const float* b1    = (const float*)d_in[6];
    const float* W2    = (const float*)d_in[7];
    const float* b2    = (const float*)d_in[8];
    const float* g1    = (const float*)d_in[9];
    const float* be1   = (const float*)d_in[10];
    const float* g2    = (const float*)d_in[11];
    const float* be2   = (const float*)d_in[12];
    const float* g3    = (const float*)d_in[13];
    const float* be3   = (const float*)d_in[14];
    const float* g4    = (const float*)d_in[15];
    const float* be4   = (const float*)d_in[16];

    static bool attr_done = false;
    if (!attr_done) {
        cudaFuncSetAttribute(gemm_cp<128,128,false,2,4>,
                             cudaFuncAttributeMaxDynamicSharedMemorySize, SMEM_NN128);
        cudaFuncSetAttribute(gemm_cp<128,128,true,2,4>,
                             cudaFuncAttributeMaxDynamicSharedMemorySize, SMEM_NT128);
        cudaFuncSetAttribute(gemm_cp<128,64,false,2,2>,
                             cudaFuncAttributeMaxDynamicSharedMemorySize, SMEM_NN64);
        attr_done = true;
    }

    float *p_h, *p_q, *p_k, *p_v, *p_att, *p_merged, *p_oproj,
          *p_r1, *p_f, *p_ff, *p_f2, *p_x;
    float *w_qkv, *w_p, *w_1, *w_2;
    cudaGetSymbolAddress((void**)&p_h, g_h);
    cudaGetSymbolAddress((void**)&p_q, g_q);
    cudaGetSymbolAddress((void**)&p_k, g_k);
    cudaGetSymbolAddress((void**)&p_v, g_v);
    cudaGetSymbolAddress((void**)&p_att, g_att);
    cudaGetSymbolAddress((void**)&p_merged, g_merged);
    cudaGetSymbolAddress((void**)&p_oproj, g_oproj);
    cudaGetSymbolAddress((void**)&p_r1, g_r1);
    cudaGetSymbolAddress((void**)&p_f, g_f);
    cudaGetSymbolAddress((void**)&p_ff, g_ff);
    cudaGetSymbolAddress((void**)&p_f2, g_f2);
    cudaGetSymbolAddress((void**)&p_x, g_x);
    cudaGetSymbolAddress((void**)&w_qkv, g_Wqkv_t);
    cudaGetSymbolAddress((void**)&w_p, g_Wp_t);
    cudaGetSymbolAddress((void**)&w_1, g_W1_t);
    cudaGetSymbolAddress((void**)&w_2, g_W2_t);

    // pre-round all weights to tf32 (once per launch)
    {
        long long n;
        n = (long long)L_*E_*E3_ / 4;
        cvt_tf32_kernel<<<(unsigned)((n + 255) / 256), 256>>>(Wqkv, w_qkv, n);
        n = (long long)L_*E_*E_ / 4;
        cvt_tf32_kernel<<<(unsigned)((n + 255) / 256), 256>>>(Wp, w_p, n);
        n = (long long)L_*E_*FF_ / 4;
        cvt_tf32_kernel<<<(unsigned)((n + 255) / 256), 256>>>(W1, w_1, n);
        n = (long long)L_*FF_*E_ / 4;
        cvt_tf32_kernel<<<(unsigned)((n + 255) / 256), 256>>>(W2, w_2, n);
    }

    cudaMemcpyAsync(p_x, x_in, (size_t)NTOK * E_ * sizeof(float),
                    cudaMemcpyDeviceToDevice, 0);

    for (int l = 0; l < L_; ++l) {
        const float* Wqkv_l = w_qkv + (long long)l * E_ * E3_;
        const float* bqkv_l = bqkv + (long long)l * E3_;
        const float* Wp_l   = w_p  + (long long)l * E_ * E_;
        const float* bp_l   = bp   + (long long)l * E_;
        const float* W1_l   = w_1  + (long long)l * E_ * FF_;
        const float* b1_l   = b1   + (long long)l * FF_;
        const float* W2_l   = w_2  + (long long)l * FF_ * E_;
        const float* b2_l   = b2   + (long long)l * E_;
        const float* g1_l = g1 + (long long)l * E_, *be1_l = be1 + (long long)l * E_;
        const float* g2_l = g2 + (long long)l * E_, *be2_l = be2 + (long long)l * E_;
        const float* g3_l = g3 + (long long)l * E_, *be3_l = be3 + (long long)l * E_;
        const float* g4_l = g4 + (long long)l * E_, *be4_l = be4 + (long long)l * E_;

        // h = LN1(x), tf32-rounded
        ln_kernel<<<NTOK, 256>>>(p_x, g1_l, be1_l, nullptr, nullptr, p_h, 1);
        // qkv = h @ Wqkv + bqkv  -> fused split into q,k,v (tf32-rounded)
        gemm_cp<128,128,false,2,4><<<dim3(E3_/128, NTOK/128, 1), 256, SMEM_NN128>>>(
            p_h, Wqkv_l, bqkv_l, nullptr, NTOK, E3_, E_, 0, 0, 0, 2, p_q, p_k, p_v);
        // energy = Q @ K^T   (batched)
        gemm_cp<128,128,true,2,4><<<dim3(S_/128, S_/128, BH), 256, SMEM_NT128>>>(
            p_q, p_k, nullptr, p_att, S_, S_, D_,
            (long long)S_*D_, (long long)S_*D_, (long long)S_*S_, 0,
            nullptr, nullptr, nullptr);
        // att = softmax(energy) / sqrt(E), tf32-rounded
        softmax_div<<<BH * S_, 256>>>(p_att);
        // O = att @ V  -> fused merge-heads into p_merged (tf32-rounded)
        gemm_cp<128,64,false,2,2><<<dim3(1, S_/128, BH), 128, SMEM_NN64>>>(
            p_att, p_v, nullptr, p_merged, S_, D_, S_,
            (long long)S_*S_, (long long)S_*D_, 0, 3, nullptr, nullptr, nullptr);
        // oproj = merged @ Wp + bp
        gemm_cp<128,128,false,2,4><<<dim3(E_/128, NTOK/128, 1), 256, SMEM_NN128>>>(
            p_merged, Wp_l, bp_l, p_oproj, NTOK, E_, E_, 0, 0, 0, 0,
            nullptr, nullptr, nullptr);
        // r1 = LN2(oproj) + x
        ln_kernel<<<NTOK, 256>>>(p_oproj, g2_l, be2_l, p_x, nullptr, p_r1, 0);
        // f = LN3(r1), tf32-rounded
        ln_kernel<<<NTOK, 256>>>(p_r1, g3_l, be3_l, nullptr, nullptr, p_f, 1);
        // ff = gelu(f @ W1 + b1), tf32-rounded
        gemm_cp<128,128,false,2,4><<<dim3(FF_/128, NTOK/128, 1), 256, SMEM_NN128>>>(
            p_f, W1_l, b1_l, p_ff, NTOK, FF_, E_, 0, 0, 0, 1,
            nullptr, nullptr, nullptr);
        // f2 = ff @ W2 + b2
        gemm_cp<128,128,false,2,4><<<dim3(E_/128, NTOK/128, 1), 256, SMEM_NN128>>>(
            p_ff, W2_l, b2_l, p_f2, NTOK, E_, FF_, 0, 0, 0, 0,
            nullptr, nullptr, nullptr);
        // x = LN4(f2) + r1 + x
        ln_kernel<<<NTOK, 256>>>(p_f2, g4_l, be4_l, p_r1, p_x, p_x, 0);
    }

    cudaMemcpyAsync(d_out, p_x, (size_t)NTOK * E_ * sizeof(float),
                    cudaMemcpyDeviceToDevice, 0);
}